// round 4
// baseline (speedup 1.0000x reference)
#include <cuda_runtime.h>
#include <math.h>

// HolographicFMLayer: out[b,p,n] = sum_k X[b,i_p,k] * X[b,j_p,(n-k) mod 64]
// for the 276 pairs (i<j) over 24 fields, batch 2048, dim 64.
// Direct circular convolution (exact fp32), FFMA-pipe-bound design:
//  - block = one batch element; fields duplicated circularly in smem
//  - 16 lanes per pair, 4 outputs per lane (float4 acc)
//  - k-loop step 4 with sliding 2x float4 register window -> 16 FMA per 2 LDS.128
//  - pair -> (i,j) via branch-free closed-form decode (exact at boundaries)

#define NF     24
#define NPAIR  276
#define DSTRIDE 132   // padded row stride (floats), 16B-aligned, breaks bank phase

__global__ __launch_bounds__(256, 4)
void holo_conv_kernel(const float* __restrict__ in, float* __restrict__ out) {
    __shared__ float D[NF][DSTRIDE];

    const int b = blockIdx.x;
    const float* __restrict__ Xb = in + (size_t)b * (NF * 64);

    // Build duplicated circular copies: D[f][m] = X[b][f][m mod 64], m in [0,128)
    for (int idx = threadIdx.x; idx < NF * 128; idx += 256) {
        int f = idx >> 7;
        int m = idx & 127;
        D[f][m] = Xb[(f << 6) + (m & 63)];
    }
    __syncthreads();

    const int warp = threadIdx.x >> 5;
    const int lane = threadIdx.x & 31;
    const int half = lane >> 4;     // which of the 2 pairs this warp handles
    const int s    = lane & 15;     // sub-lane within pair
    const int n0   = s << 2;        // 4 outputs starting at n0

    for (int c = warp; c < NPAIR / 2; c += 8) {
        const int p = 2 * c + half;

        // Closed-form decode of upper-triangle pair index (row-major, k=1):
        // start(i) = i*(47-i)/2 ; i = floor((47 - sqrt(2209 - 8p)) / 2).
        // 2209-8p is an exact fp32 integer; sqrtf is correctly rounded, so
        // perfect-square boundaries decode exactly.
        const float disc = (float)(2209 - 8 * p);
        int i = (int)((47.0f - sqrtf(disc)) * 0.5f);
        // guard against any 1-ulp slip (branch-free fixups, normally no-ops)
        if (((i + 1) * (46 - i)) >> 1 <= p) i++;
        if ((i * (47 - i)) >> 1 > p) i--;
        const int j = p - ((i * (47 - i)) >> 1) + i + 1;

        const float* __restrict__ Ai = &D[i][0];
        const float* __restrict__ Dj = &D[j][0];

        float4 acc = make_float4(0.f, 0.f, 0.f, 0.f);
        // Qb holds D[j][64+n0-4t .. +3], Qa holds D[j][60+n0-4t .. +3]
        float4 Qb = *reinterpret_cast<const float4*>(Dj + 64 + n0);

        #pragma unroll
        for (int t = 0; t < 16; t++) {
            const float4 a4 = *reinterpret_cast<const float4*>(Ai + 64 + 4 * t);
            const float4 Qa = *reinterpret_cast<const float4*>(Dj + 60 + n0 - 4 * t);

            // k = 4t   : window aligned -> Qb
            acc.x = fmaf(a4.x, Qb.x, acc.x);
            acc.y = fmaf(a4.x, Qb.y, acc.y);
            acc.z = fmaf(a4.x, Qb.z, acc.z);
            acc.w = fmaf(a4.x, Qb.w, acc.w);
            // k = 4t+1
            acc.x = fmaf(a4.y, Qa.w, acc.x);
            acc.y = fmaf(a4.y, Qb.x, acc.y);
            acc.z = fmaf(a4.y, Qb.y, acc.z);
            acc.w = fmaf(a4.y, Qb.z, acc.w);
            // k = 4t+2
            acc.x = fmaf(a4.z, Qa.z, acc.x);
            acc.y = fmaf(a4.z, Qa.w, acc.y);
            acc.z = fmaf(a4.z, Qb.x, acc.z);
            acc.w = fmaf(a4.z, Qb.y, acc.w);
            // k = 4t+3
            acc.x = fmaf(a4.w, Qa.y, acc.x);
            acc.y = fmaf(a4.w, Qa.z, acc.y);
            acc.z = fmaf(a4.w, Qa.w, acc.z);
            acc.w = fmaf(a4.w, Qb.x, acc.w);

            Qb = Qa;  // slide window (renamed away by full unroll)
        }

        float4* o = reinterpret_cast<float4*>(
            out + ((size_t)b * NPAIR + p) * 64 + n0);
        *o = acc;
    }
}

extern "C" void kernel_launch(void* const* d_in, const int* in_sizes, int n_in,
                              void* d_out, int out_size) {
    const float* in = (const float*)d_in[0];
    float* out = (float*)d_out;
    (void)in_sizes; (void)n_in; (void)out_size;
    holo_conv_kernel<<<2048, 256>>>(in, out);
}